// round 3
// baseline (speedup 1.0000x reference)
#include <cuda_runtime.h>
#include <math.h>
#include <stdint.h>

// Problem constants
#define BATCH 1024
#define TT    256
#define FF    128
#define HH    256
#define GG    1024   // 4*H
#define OO    50

// ---------------------------------------------------------------------------
// Static device scratch (allocation-free per harness rules)
// ---------------------------------------------------------------------------
__device__ float g_xz[(size_t)TT * BATCH * GG];      // 1 GiB, [t][b][g]; reused for layer0 then layer1
__device__ float g_h0seq[(size_t)TT * BATCH * HH];   // 256 MB, [t][b][h]
__device__ float g_hbuf[2][BATCH * HH];              // double-buffered h state
__device__ unsigned g_barc = 0;
__device__ unsigned g_barg = 0;

// ---------------------------------------------------------------------------
// Grid-wide barrier (all blocks resident by construction: 256 blocks,
// ~89KB smem each -> exactly 2 blocks/SM, capacity 2*148=296 >= 256)
// ---------------------------------------------------------------------------
__device__ __forceinline__ void gbar() {
    __syncthreads();
    if (threadIdx.x == 0) {
        __threadfence();
        unsigned gen = *((volatile unsigned*)&g_barg);
        if (atomicAdd(&g_barc, 1) == gridDim.x - 1) {
            atomicExch(&g_barc, 0);
            __threadfence();
            atomicExch(&g_barg, gen + 1);
        } else {
            while (*((volatile unsigned*)&g_barg) == gen) { __nanosleep(32); }
        }
        __threadfence();
    }
    __syncthreads();
}

__device__ __forceinline__ float sigf(float x) { return 1.0f / (1.0f + expf(-x)); }

// ---------------------------------------------------------------------------
// SGEMM with bias: C = A[M,K] @ B[K,N] + bias[N]
// BM=128, BN=64, BK=16, 256 threads, 8x4 per-thread microtile.
// PERM=true: A rows are m=b*T+t (x layout), output rows written to t*BATCH+b
//            so xz lands in [t][b][g] layout for the recurrent kernel.
// ---------------------------------------------------------------------------
template<bool PERM>
__global__ __launch_bounds__(256) void sgemm_bias(
    const float* __restrict__ A, const float* __restrict__ Bm,
    const float* __restrict__ bias, float* __restrict__ C,
    int M, int N, int K)
{
    __shared__ __align__(16) float As[16 * 132];   // [k][m] transposed, padded
    __shared__ __align__(16) float Bs[16 * 64];    // [k][n]

    const int tid = threadIdx.x;
    const int tx = tid & 15;        // col group 0..15 -> cols tx*4..+3
    const int ty = tid >> 4;        // row group 0..15 -> rows ty*8..+7
    const int m0 = blockIdx.y * 128;
    const int n0 = blockIdx.x * 64;

    float acc[8][4];
#pragma unroll
    for (int i = 0; i < 8; ++i)
#pragma unroll
        for (int j = 0; j < 4; ++j) acc[i][j] = 0.0f;

    for (int k0 = 0; k0 < K; k0 += 16) {
        // Load A tile 128x16 (512 float4, 2 per thread), store transposed
#pragma unroll
        for (int q = 0; q < 2; ++q) {
            int f4 = tid * 2 + q;
            int r  = f4 >> 2;
            int c4 = (f4 & 3) * 4;
            float4 v = *(const float4*)(A + (size_t)(m0 + r) * K + k0 + c4);
            As[(c4 + 0) * 132 + r] = v.x;
            As[(c4 + 1) * 132 + r] = v.y;
            As[(c4 + 2) * 132 + r] = v.z;
            As[(c4 + 3) * 132 + r] = v.w;
        }
        // Load B tile 16x64 (256 float4, 1 per thread)
        {
            int r  = tid >> 4;
            int c4 = (tid & 15) * 4;
            *(float4*)(Bs + r * 64 + c4) =
                *(const float4*)(Bm + (size_t)(k0 + r) * N + n0 + c4);
        }
        __syncthreads();

#pragma unroll
        for (int kk = 0; kk < 16; ++kk) {
            float4 a0 = *(const float4*)(As + kk * 132 + ty * 8);
            float4 a1 = *(const float4*)(As + kk * 132 + ty * 8 + 4);
            float4 b4 = *(const float4*)(Bs + kk * 64 + tx * 4);
            float av[8] = {a0.x, a0.y, a0.z, a0.w, a1.x, a1.y, a1.z, a1.w};
#pragma unroll
            for (int i = 0; i < 8; ++i) {
                acc[i][0] = fmaf(av[i], b4.x, acc[i][0]);
                acc[i][1] = fmaf(av[i], b4.y, acc[i][1]);
                acc[i][2] = fmaf(av[i], b4.z, acc[i][2]);
                acc[i][3] = fmaf(av[i], b4.w, acc[i][3]);
            }
        }
        __syncthreads();
    }

    float4 bb = *(const float4*)(bias + n0 + tx * 4);
#pragma unroll
    for (int i = 0; i < 8; ++i) {
        size_t m = (size_t)(m0 + ty * 8 + i);
        size_t orow = PERM ? ((m % TT) * (size_t)BATCH + (m / TT)) : m;
        float4 o;
        o.x = acc[i][0] + bb.x;
        o.y = acc[i][1] + bb.y;
        o.z = acc[i][2] + bb.z;
        o.w = acc[i][3] + bb.w;
        *(float4*)(C + orow * (size_t)N + n0 + tx * 4) = o;
    }
}

// ---------------------------------------------------------------------------
// Persistent LSTM layer kernel. Grid = 256 blocks (16 batch-chunks x 16
// h-chunks), 256 threads. Each block owns batch rows [bi*64, bi*64+64) and
// hidden cols [hj*16, hj*16+16), including ALL FOUR gate columns for those
// hidden indices -> the full cell update is local (c stays in registers).
// U slice (256 x 64 cols, gate-interleaved) lives in SMEM for the whole layer.
// h state double-buffered in global; one grid barrier per timestep.
// ---------------------------------------------------------------------------
__global__ __launch_bounds__(256, 2) void lstm_rec(
    const float* __restrict__ xz,     // [T][B][G]
    const float* __restrict__ U,      // [H][G] row-major
    float* __restrict__ seqout)       // [T][B][H] or nullptr
{
    extern __shared__ __align__(16) float sm[];
    float* Us = sm;                   // 256*64 = 16384 floats
    float* hs = Us + 256 * 64;        // 64 rows x 32 k     = 2048 floats
    float* zs = hs + 64 * 32;         // 64 rows x 68 (pad) = 4352 floats

    const int tid = threadIdx.x;
    const int bi  = blockIdx.x >> 4;  // batch chunk
    const int hj  = blockIdx.x & 15;  // hidden chunk

    // Load U slice: local col c -> global col (c/16)*HH + hj*16 + (c%16)
    for (int idx = tid; idx < 256 * 64; idx += 256) {
        int k = idx >> 6, c = idx & 63;
        int gcol = (c >> 4) * HH + hj * 16 + (c & 15);
        Us[idx] = U[(size_t)k * GG + gcol];
    }

    // Zero this block's portion of h-state buffer 0 (read at t=0)
    {
        int r = tid >> 2, h0 = (tid & 3) * 4;
#pragma unroll
        for (int p = 0; p < 4; ++p)
            g_hbuf[0][(size_t)(bi * 64 + r) * HH + hj * 16 + h0 + p] = 0.0f;
    }
    gbar();

    const int rx = tid & 15;                    // GEMM col group
    const int ry = tid >> 4;                    // GEMM row group
    const int gcol0 = (rx >> 2) * HH + hj * 16 + (rx & 3) * 4;
    const int er  = tid >> 2;                   // elementwise row 0..63
    const int eh0 = (tid & 3) * 4;              // elementwise h offset

    float creg[4] = {0.0f, 0.0f, 0.0f, 0.0f};   // cell state, registers

    for (int t = 0; t < TT; ++t) {
        const float* hin  = g_hbuf[t & 1];
        float*       hout = g_hbuf[(t + 1) & 1];

        float acc[4][4];
#pragma unroll
        for (int i = 0; i < 4; ++i)
#pragma unroll
            for (int j = 0; j < 4; ++j) acc[i][j] = 0.0f;

        // z = h @ Uslice   (64x64 tile, K=256 in chunks of 32)
        for (int k0 = 0; k0 < HH; k0 += 32) {
            __syncthreads();
#pragma unroll
            for (int q = 0; q < 2; ++q) {
                int f4 = tid * 2 + q;
                int r  = f4 >> 3;
                int c4 = (f4 & 7) * 4;
                *(float4*)(hs + r * 32 + c4) =
                    *(const float4*)(hin + (size_t)(bi * 64 + r) * HH + k0 + c4);
            }
            __syncthreads();
#pragma unroll
            for (int kk = 0; kk < 32; ++kk) {
                float4 b4 = *(const float4*)(Us + (k0 + kk) * 64 + rx * 4);
#pragma unroll
                for (int i = 0; i < 4; ++i) {
                    float a = hs[(ry * 4 + i) * 32 + kk];
                    acc[i][0] = fmaf(a, b4.x, acc[i][0]);
                    acc[i][1] = fmaf(a, b4.y, acc[i][1]);
                    acc[i][2] = fmaf(a, b4.z, acc[i][2]);
                    acc[i][3] = fmaf(a, b4.w, acc[i][3]);
                }
            }
        }
        __syncthreads();

        // z += xz[t], exchange through SMEM so each thread sees all 4 gates
#pragma unroll
        for (int i = 0; i < 4; ++i) {
            int r  = ry * 4 + i;
            int bg = bi * 64 + r;
            float4 xv = *(const float4*)(xz + ((size_t)t * BATCH + bg) * GG + gcol0);
            float4 zv;
            zv.x = acc[i][0] + xv.x;
            zv.y = acc[i][1] + xv.y;
            zv.z = acc[i][2] + xv.z;
            zv.w = acc[i][3] + xv.w;
            *(float4*)(zs + r * 68 + rx * 4) = zv;
        }
        __syncthreads();

        // Gate nonlinearities + state update (gate order i,f,g,o)
#pragma unroll
        for (int p = 0; p < 4; ++p) {
            int ho = eh0 + p;
            float zi = zs[er * 68 +      ho];
            float zf = zs[er * 68 + 16 + ho];
            float zg = zs[er * 68 + 32 + ho];
            float zo = zs[er * 68 + 48 + ho];
            float cc = sigf(zf) * creg[p] + sigf(zi) * tanhf(zg);
            creg[p]  = cc;
            float hh = sigf(zo) * tanhf(cc);
            int bg  = bi * 64 + er;
            int col = hj * 16 + ho;
            hout[(size_t)bg * HH + col] = hh;
            if (seqout) seqout[((size_t)t * BATCH + bg) * HH + col] = hh;
        }
        gbar();   // publish h for next step
    }
    // final h (t=255) lives in g_hbuf[0]
}

// ---------------------------------------------------------------------------
// Head: logits = h @ Wout + bout; softmax; capped-simplex water-filling
// (bit-faithful to reference: exact !=0.1f mask, freeze-on-done, 50 iters).
// One block per batch row.
// ---------------------------------------------------------------------------
__device__ __forceinline__ float clip01(float x) {
    return fminf(fmaxf(x, 0.0f), 0.1f);
}
__device__ __forceinline__ float wsum(float v) {
#pragma unroll
    for (int o = 16; o > 0; o >>= 1) v += __shfl_xor_sync(0xffffffffu, v, o);
    return v;
}
__device__ __forceinline__ float wmax(float v) {
#pragma unroll
    for (int o = 16; o > 0; o >>= 1) v = fmaxf(v, __shfl_xor_sync(0xffffffffu, v, o));
    return v;
}

__global__ __launch_bounds__(64) void head_kernel(
    const float* __restrict__ Wout, const float* __restrict__ bout,
    float* __restrict__ out)
{
    __shared__ float hsh[HH];
    __shared__ float lg[OO];
    const int b = blockIdx.x;
    const int tid = threadIdx.x;

    for (int i = tid; i < HH; i += 64) hsh[i] = g_hbuf[0][(size_t)b * HH + i];
    __syncthreads();

    if (tid < OO) {
        float a = bout[tid];
        for (int k = 0; k < HH; ++k) a = fmaf(hsh[k], Wout[(size_t)k * OO + tid], a);
        lg[tid] = a;
    }
    __syncthreads();

    if (tid < 32) {
        const bool has1 = (tid + 32) < OO;
        float v0 = lg[tid];
        float v1 = has1 ? lg[tid + 32] : -INFINITY;

        float m  = wmax(fmaxf(v0, v1));
        float e0 = expf(v0 - m);
        float e1 = has1 ? expf(v1 - m) : 0.0f;
        float s  = wsum(e0 + e1);
        float w0 = e0 / s, w1 = e1 / s;   // w1 == 0 on padding lanes (inert below)

        float old0 = w0, old1 = w1;
        float wc0 = clip01(w0), wc1 = clip01(w1);
        bool done = false;

        for (int it = 0; it < 50; ++it) {
            float leftover = wsum((old0 - wc0) + (old1 - wc1));
            bool m0 = (wc0 != 0.1f), m1 = (wc1 != 0.1f);
            float n0 = m0 ? wc0 : 0.0f;
            float n1 = m1 ? wc1 : 0.0f;
            float denom = wsum(n0 + n1);
            float dd = (denom == 0.0f) ? 1.0f : denom;
            float wn0 = m0 ? wc0 + leftover * n0 / dd : wc0;
            float wn1 = m1 ? wc1 + leftover * n1 / dd : wc1;
            bool over = __any_sync(0xffffffffu, (wn0 > 0.1f) || (wn1 > 0.1f));
            bool ndone = !over;
            float wx0 = ndone ? wn0 : clip01(wn0);
            float wx1 = ndone ? wn1 : clip01(wn1);
            if (!done) { old0 = wn0; old1 = wn1; wc0 = wx0; wc1 = wx1; }
            done = done || ndone;
        }

        out[(size_t)b * OO + tid] = wc0;
        if (has1) out[(size_t)b * OO + tid + 32] = wc1;
    }
}

// ---------------------------------------------------------------------------
// Launch (graph-capturable: kernel launches only)
// ---------------------------------------------------------------------------
extern "C" void kernel_launch(void* const* d_in, const int* in_sizes, int n_in,
                              void* d_out, int out_size)
{
    const float* x    = (const float*)d_in[0];
    const float* W0   = (const float*)d_in[1];
    const float* U0   = (const float*)d_in[2];
    const float* b0   = (const float*)d_in[3];
    const float* W1   = (const float*)d_in[4];
    const float* U1   = (const float*)d_in[5];
    const float* b1   = (const float*)d_in[6];
    const float* Wout = (const float*)d_in[7];
    const float* bout = (const float*)d_in[8];
    float* out = (float*)d_out;

    float *p_xz = nullptr, *p_h0 = nullptr;
    cudaGetSymbolAddress((void**)&p_xz, g_xz);
    cudaGetSymbolAddress((void**)&p_h0, g_h0seq);

    const int REC_SMEM = (256 * 64 + 64 * 32 + 64 * 68) * (int)sizeof(float); // 91136
    cudaFuncSetAttribute(lstm_rec, cudaFuncAttributeMaxDynamicSharedMemorySize, REC_SMEM);

    dim3 gg(GG / 64, (BATCH * TT) / 128);   // (16, 2048)

    // Layer 0 input projection: xz0[t][b][g]
    sgemm_bias<true><<<gg, 256>>>(x, W0, b0, p_xz, BATCH * TT, GG, FF);
    // Layer 0 recurrence -> h0seq[t][b][h]
    lstm_rec<<<256, 256, REC_SMEM>>>(p_xz, U0, p_h0);
    // Layer 1 input projection: xz1[t][b][g] (reuses g_xz)
    sgemm_bias<false><<<gg, 256>>>(p_h0, W1, b1, p_xz, BATCH * TT, GG, HH);
    // Layer 1 recurrence (final h ends in g_hbuf[0])
    lstm_rec<<<256, 256, REC_SMEM>>>(p_xz, U1, nullptr);
    // Head: logits -> softmax -> rebalance
    head_kernel<<<BATCH, 64>>>(Wout, bout, out);
}